// round 3
// baseline (speedup 1.0000x reference)
#include <cuda_runtime.h>

#define BATCH 2048
#define ISIZE 2048
#define OSIZE 2048
#define NIN   6
#define KTAB  64

typedef unsigned long long ull;

// Static scratch: transposed x, xT[m][b]  (16 MB)
__device__ float g_xT[(size_t)ISIZE * BATCH];
// Canonical int32 mapping (converted from int32 or int64 source)
__device__ int g_map[(size_t)OSIZE * NIN];

__device__ __forceinline__ ull pack2(float lo, float hi) {
    ull r;
    asm("mov.b64 %0, {%1, %2};" : "=l"(r) : "f"(lo), "f"(hi));
    return r;
}
__device__ __forceinline__ ull fma2(ull a, ull b, ull c) {
    ull r;
    asm("fma.rn.f32x2 %0, %1, %2, %3;" : "=l"(r) : "l"(a), "l"(b), "l"(c));
    return r;
}
__device__ __forceinline__ float2 unpack2(ull v) {
    float2 f;
    asm("mov.b64 {%0, %1}, %2;" : "=f"(f.x), "=f"(f.y) : "l"(v));
    return f;
}

// ---------------------------------------------------------------------------
// Kernel 0: detect mapping dtype (int32 vs int64) and convert to g_map.
// If int64 little-endian with values < 2048, every odd int32 word is 0.
// Probability of 32 consecutive odd words all being 0 under the int32
// hypothesis (uniform [0,2048)) is ~2048^-32 — effectively impossible.
// All reads stay within the smaller (int32) buffer size (12288 words).
// ---------------------------------------------------------------------------
__global__ void convert_mapping_kernel(const void* __restrict__ mraw) {
    __shared__ int s_is64;
    const int* w = (const int*)mraw;
    if (threadIdx.x == 0) {
        int all_zero = 1;
        for (int i = 1; i < 64; i += 2) all_zero &= (w[i] == 0);
        s_is64 = all_zero;
    }
    __syncthreads();
    const int is64 = s_is64;
    const int total = OSIZE * NIN;
    for (int idx = blockIdx.x * blockDim.x + threadIdx.x; idx < total;
         idx += gridDim.x * blockDim.x) {
        int m = is64 ? (int)((const long long*)mraw)[idx] : w[idx];
        g_map[idx] = m;
    }
}

// ---------------------------------------------------------------------------
// Kernel 1: transpose x [BATCH][ISIZE] -> g_xT [ISIZE][BATCH]
// ---------------------------------------------------------------------------
__global__ void transpose_kernel(const float* __restrict__ x) {
    __shared__ float tile[32][33];
    int bx = blockIdx.x * 32;   // input-feature (m) base
    int by = blockIdx.y * 32;   // batch base
    int tx = threadIdx.x, ty = threadIdx.y;
#pragma unroll
    for (int j = 0; j < 32; j += 8)
        tile[ty + j][tx] = x[(size_t)(by + ty + j) * ISIZE + bx + tx];
    __syncthreads();
#pragma unroll
    for (int j = 0; j < 32; j += 8)
        g_xT[(size_t)(bx + ty + j) * BATCH + by + tx] = tile[tx][ty + j];
}

// ---------------------------------------------------------------------------
// Kernel 2: main LUT evaluation.
//   CTA tile: 32 outputs x 256 batches (128 threads, 2 batches/thread, f32x2).
//   6 lerp levels LSB-first; level 0 is one FFMA2 per table pair
//   (delta precomputed), levels 1..5 are 2 FFMA2 per lerp.
// ---------------------------------------------------------------------------
#define OT      32
#define THREADS 128
#define BT      (2 * THREADS)

__global__ __launch_bounds__(THREADS)
void lut_kernel(const float* __restrict__ table,
                float* __restrict__ out) {
    __shared__ float2 s_sd[OT][KTAB / 2];   // (sig(s[2k]), sig(s[2k+1])-sig(s[2k]))
    __shared__ int    s_off[OT][NIN];       // m*BATCH + bbase

    const int tid   = threadIdx.x;
    const int obase = blockIdx.x * OT;
    const int bbase = blockIdx.y * BT;

    for (int p = tid; p < OT * (KTAB / 2); p += THREADS) {
        int o = p >> 5, k = p & 31;
        float t0 = table[(size_t)(obase + o) * KTAB + 2 * k];
        float t1 = table[(size_t)(obase + o) * KTAB + 2 * k + 1];
        float a = 1.0f / (1.0f + __expf(-t0));
        float b = 1.0f / (1.0f + __expf(-t1));
        s_sd[o][k] = make_float2(a, b - a);
    }
    for (int p = tid; p < OT * NIN; p += THREADS) {
        int o = p / NIN, i = p % NIN;
        s_off[o][i] = g_map[(obase + o) * NIN + i] * BATCH + bbase;
    }
    __syncthreads();

    const ull NEG1 = pack2(-1.0f, -1.0f);
    const int bl = 2 * tid;

    float rlo[8], rhi[8];

    for (int og = 0; og < OT / 8; og++) {
#pragma unroll
        for (int oj = 0; oj < 8; oj++) {
            const int o = og * 8 + oj;

            ull xv[NIN];
#pragma unroll
            for (int i = 0; i < NIN; i++) {
                const float* p = g_xT + s_off[o][i] + bl;
                xv[i] = *(const ull*)p;
            }

            ull acc[32];
#pragma unroll
            for (int k = 0; k < 32; k++) {
                float2 sd = s_sd[o][k];
                acc[k] = fma2(xv[0], pack2(sd.y, sd.y), pack2(sd.x, sd.x));
            }

#pragma unroll
            for (int lvl = 1; lvl < 6; lvl++) {
                const int n = 32 >> lvl;
#pragma unroll
                for (int k = 0; k < n; k++) {
                    ull d = fma2(acc[2 * k], NEG1, acc[2 * k + 1]);  // b - a
                    acc[k] = fma2(xv[lvl], d, acc[2 * k]);           // a + x*(b-a)
                }
            }

            float2 r = unpack2(acc[0]);
            rlo[oj] = r.x;
            rhi[oj] = r.y;
        }

        float4* p0 = (float4*)(out + (size_t)(bbase + bl) * OSIZE + obase + og * 8);
        float4* p1 = (float4*)(out + (size_t)(bbase + bl + 1) * OSIZE + obase + og * 8);
        p0[0] = make_float4(rlo[0], rlo[1], rlo[2], rlo[3]);
        p0[1] = make_float4(rlo[4], rlo[5], rlo[6], rlo[7]);
        p1[0] = make_float4(rhi[0], rhi[1], rhi[2], rhi[3]);
        p1[1] = make_float4(rhi[4], rhi[5], rhi[6], rhi[7]);
    }
}

// ---------------------------------------------------------------------------
extern "C" void kernel_launch(void* const* d_in, const int* in_sizes, int n_in,
                              void* d_out, int out_size) {
    const float* x     = (const float*)d_in[0];
    const float* table = (const float*)d_in[1];
    const void*  mraw  = d_in[2];
    float*       out   = (float*)d_out;

    (void)in_sizes; (void)n_in; (void)out_size;

    convert_mapping_kernel<<<32, 384>>>(mraw);
    transpose_kernel<<<dim3(ISIZE / 32, BATCH / 32), dim3(32, 8)>>>(x);
    lut_kernel<<<dim3(OSIZE / OT, BATCH / BT), THREADS>>>(table, out);
}